// round 12
// baseline (speedup 1.0000x reference)
#include <cuda_runtime.h>
#include <cuda_fp16.h>
#include <cstdint>

// Problem constants
#define NNODES 50000
#define NEDGES 800000
#define IN_C   256
#define OUT_C  128
#define PAD    64            // Poisson(16): P(deg >= 64) ~ 1e-20 per node

// Scratch
__device__ __align__(16) __half g_y[NNODES * OUT_C];  // linear output, fp16 (12.8 MB)
__device__ __align__(16) int g_cnt[NNODES];           // zero at entry (consumer-reset)
__device__ __align__(16) int g_pad[NNODES * PAD];     // padded buckets (12.8 MB)

// ---------------------------------------------------------------------------
// K1: fused rank + store — the ONLY build kernel. 4 edges/thread via int4.
// ---------------------------------------------------------------------------
__global__ __launch_bounds__(256) void build_kernel(const int* __restrict__ ei) {
    int t = blockIdx.x * blockDim.x + threadIdx.x;
    int base = t * 4;
    if (base >= NEDGES) return;
    int4 s = *reinterpret_cast<const int4*>(ei + base);
    int4 d = *reinterpret_cast<const int4*>(ei + NEDGES + base);
    int r0 = atomicAdd(&g_cnt[d.x], 1);
    int r1 = atomicAdd(&g_cnt[d.y], 1);
    int r2 = atomicAdd(&g_cnt[d.z], 1);
    int r3 = atomicAdd(&g_cnt[d.w], 1);
    if (r0 < PAD) g_pad[d.x * PAD + r0] = s.x;
    if (r1 < PAD) g_pad[d.y * PAD + r1] = s.y;
    if (r2 < PAD) g_pad[d.z * PAD + r2] = s.z;
    if (r3 < PAD) g_pad[d.w * PAD + r3] = s.w;
}

// ---------------------------------------------------------------------------
// K2: tf32 tensor-core GEMM, double-buffered smem.
// y[m,n] = sum_k x[m,k] * W[n,k] + b[n], fp16 out.
// ---------------------------------------------------------------------------
#define GBM 128
#define GBK 16
#define SSTRIDE 136
#define NTILES (IN_C / GBK)   // 16

__device__ __forceinline__ uint32_t f32_to_tf32(float f) {
    uint32_t r;
    asm("cvt.rna.tf32.f32 %0, %1;" : "=r"(r) : "f"(f));
    return r;
}

__global__ __launch_bounds__(256, 2) void gemm_tf32_kernel(
    const float* __restrict__ x,
    const float* __restrict__ W,
    const float* __restrict__ b)
{
    __shared__ uint32_t As[2][GBK * SSTRIDE];
    __shared__ uint32_t Bs[2][GBK * SSTRIDE];

    const int tid  = threadIdx.x;
    const int lane = tid & 31;
    const int warp = tid >> 5;
    const int wm   = warp >> 1;
    const int wn   = warp & 1;
    const int block_m = blockIdx.x * GBM;
    const int grp = lane >> 2;
    const int qid = lane & 3;

    const int idx0 = tid * 2;
    const int row0 = idx0 >> 2;
    const int kq0  = (idx0 & 3) * 4;
    const int row1 = (idx0 + 1) >> 2;
    const int kq1  = ((idx0 + 1) & 3) * 4;
    const int gm0 = block_m + row0;
    const int gm1 = block_m + row1;
    const bool ok0 = (gm0 < NNODES);
    const bool ok1 = (gm1 < NNODES);

    float acc[2][8][4];
    #pragma unroll
    for (int i = 0; i < 2; i++)
        #pragma unroll
        for (int j = 0; j < 8; j++)
            #pragma unroll
            for (int c = 0; c < 4; c++)
                acc[i][j][c] = 0.f;

    float4 pa0, pa1, pb0, pb1;

    pa0 = ok0 ? *reinterpret_cast<const float4*>(x + (size_t)gm0 * IN_C + kq0)
              : make_float4(0.f, 0.f, 0.f, 0.f);
    pa1 = ok1 ? *reinterpret_cast<const float4*>(x + (size_t)gm1 * IN_C + kq1)
              : make_float4(0.f, 0.f, 0.f, 0.f);
    pb0 = *reinterpret_cast<const float4*>(W + (size_t)row0 * IN_C + kq0);
    pb1 = *reinterpret_cast<const float4*>(W + (size_t)row1 * IN_C + kq1);

    {
        As[0][(kq0 + 0) * SSTRIDE + row0] = f32_to_tf32(pa0.x);
        As[0][(kq0 + 1) * SSTRIDE + row0] = f32_to_tf32(pa0.y);
        As[0][(kq0 + 2) * SSTRIDE + row0] = f32_to_tf32(pa0.z);
        As[0][(kq0 + 3) * SSTRIDE + row0] = f32_to_tf32(pa0.w);
        As[0][(kq1 + 0) * SSTRIDE + row1] = f32_to_tf32(pa1.x);
        As[0][(kq1 + 1) * SSTRIDE + row1] = f32_to_tf32(pa1.y);
        As[0][(kq1 + 2) * SSTRIDE + row1] = f32_to_tf32(pa1.z);
        As[0][(kq1 + 3) * SSTRIDE + row1] = f32_to_tf32(pa1.w);
        Bs[0][(kq0 + 0) * SSTRIDE + row0] = f32_to_tf32(pb0.x);
        Bs[0][(kq0 + 1) * SSTRIDE + row0] = f32_to_tf32(pb0.y);
        Bs[0][(kq0 + 2) * SSTRIDE + row0] = f32_to_tf32(pb0.z);
        Bs[0][(kq0 + 3) * SSTRIDE + row0] = f32_to_tf32(pb0.w);
        Bs[0][(kq1 + 0) * SSTRIDE + row1] = f32_to_tf32(pb1.x);
        Bs[0][(kq1 + 1) * SSTRIDE + row1] = f32_to_tf32(pb1.y);
        Bs[0][(kq1 + 2) * SSTRIDE + row1] = f32_to_tf32(pb1.z);
        Bs[0][(kq1 + 3) * SSTRIDE + row1] = f32_to_tf32(pb1.w);
    }
    __syncthreads();

    for (int t = 0; t < NTILES; t++) {
        const int cur = t & 1;
        const bool has_next = (t + 1 < NTILES);

        if (has_next) {
            int k0 = (t + 1) * GBK;
            pa0 = ok0 ? *reinterpret_cast<const float4*>(x + (size_t)gm0 * IN_C + k0 + kq0)
                      : make_float4(0.f, 0.f, 0.f, 0.f);
            pa1 = ok1 ? *reinterpret_cast<const float4*>(x + (size_t)gm1 * IN_C + k0 + kq1)
                      : make_float4(0.f, 0.f, 0.f, 0.f);
            pb0 = *reinterpret_cast<const float4*>(W + (size_t)row0 * IN_C + k0 + kq0);
            pb1 = *reinterpret_cast<const float4*>(W + (size_t)row1 * IN_C + k0 + kq1);
        }

        #pragma unroll
        for (int s = 0; s < 2; s++) {
            const int kk = s * 8 + qid;

            uint32_t af[2][4];
            #pragma unroll
            for (int i = 0; i < 2; i++) {
                int rm = wm * 32 + i * 16 + grp;
                af[i][0] = As[cur][kk * SSTRIDE + rm];
                af[i][1] = As[cur][kk * SSTRIDE + rm + 8];
                af[i][2] = As[cur][(kk + 4) * SSTRIDE + rm];
                af[i][3] = As[cur][(kk + 4) * SSTRIDE + rm + 8];
            }
            uint32_t bf[8][2];
            #pragma unroll
            for (int j = 0; j < 8; j++) {
                int bn = wn * 64 + j * 8 + grp;
                bf[j][0] = Bs[cur][kk * SSTRIDE + bn];
                bf[j][1] = Bs[cur][(kk + 4) * SSTRIDE + bn];
            }
            #pragma unroll
            for (int i = 0; i < 2; i++)
                #pragma unroll
                for (int j = 0; j < 8; j++) {
                    asm volatile(
                        "mma.sync.aligned.m16n8k8.row.col.f32.tf32.tf32.f32 "
                        "{%0,%1,%2,%3}, {%4,%5,%6,%7}, {%8,%9}, {%0,%1,%2,%3};\n"
                        : "+f"(acc[i][j][0]), "+f"(acc[i][j][1]),
                          "+f"(acc[i][j][2]), "+f"(acc[i][j][3])
                        : "r"(af[i][0]), "r"(af[i][1]), "r"(af[i][2]), "r"(af[i][3]),
                          "r"(bf[j][0]), "r"(bf[j][1]));
                }
        }

        if (has_next) {
            const int nxt = cur ^ 1;
            As[nxt][(kq0 + 0) * SSTRIDE + row0] = f32_to_tf32(pa0.x);
            As[nxt][(kq0 + 1) * SSTRIDE + row0] = f32_to_tf32(pa0.y);
            As[nxt][(kq0 + 2) * SSTRIDE + row0] = f32_to_tf32(pa0.z);
            As[nxt][(kq0 + 3) * SSTRIDE + row0] = f32_to_tf32(pa0.w);
            As[nxt][(kq1 + 0) * SSTRIDE + row1] = f32_to_tf32(pa1.x);
            As[nxt][(kq1 + 1) * SSTRIDE + row1] = f32_to_tf32(pa1.y);
            As[nxt][(kq1 + 2) * SSTRIDE + row1] = f32_to_tf32(pa1.z);
            As[nxt][(kq1 + 3) * SSTRIDE + row1] = f32_to_tf32(pa1.w);
            Bs[nxt][(kq0 + 0) * SSTRIDE + row0] = f32_to_tf32(pb0.x);
            Bs[nxt][(kq0 + 1) * SSTRIDE + row0] = f32_to_tf32(pb0.y);
            Bs[nxt][(kq0 + 2) * SSTRIDE + row0] = f32_to_tf32(pb0.z);
            Bs[nxt][(kq0 + 3) * SSTRIDE + row0] = f32_to_tf32(pb0.w);
            Bs[nxt][(kq1 + 0) * SSTRIDE + row1] = f32_to_tf32(pb1.x);
            Bs[nxt][(kq1 + 1) * SSTRIDE + row1] = f32_to_tf32(pb1.y);
            Bs[nxt][(kq1 + 2) * SSTRIDE + row1] = f32_to_tf32(pb1.z);
            Bs[nxt][(kq1 + 3) * SSTRIDE + row1] = f32_to_tf32(pb1.w);
            __syncthreads();
        }
    }

    #pragma unroll
    for (int i = 0; i < 2; i++) {
        int r0 = block_m + wm * 32 + i * 16 + grp;
        int r1 = r0 + 8;
        #pragma unroll
        for (int j = 0; j < 8; j++) {
            int col = wn * 64 + j * 8 + qid * 2;
            float b0 = b[col], b1 = b[col + 1];
            if (r0 < NNODES) {
                __half2 h = __floats2half2_rn(acc[i][j][0] + b0, acc[i][j][1] + b1);
                *reinterpret_cast<__half2*>(&g_y[(size_t)r0 * OUT_C + col]) = h;
            }
            if (r1 < NNODES) {
                __half2 h = __floats2half2_rn(acc[i][j][2] + b0, acc[i][j][3] + b1);
                *reinterpret_cast<__half2*>(&g_y[(size_t)r1 * OUT_C + col]) = h;
            }
        }
    }
}

// ---------------------------------------------------------------------------
// K3: gather + mean. ONE node per warp; lane covers 4 halfs (uint2, 8B);
// 32 lanes x 8B = one full 256B row per request. fp32 accumulation,
// unrolled x8 for MLP. Resets g_cnt for the next replay.
// ---------------------------------------------------------------------------
__device__ __forceinline__ void acc_row4(float* acc, uint2 v) {
    float2 f;
    f = __half22float2(*reinterpret_cast<__half2*>(&v.x)); acc[0] += f.x; acc[1] += f.y;
    f = __half22float2(*reinterpret_cast<__half2*>(&v.y)); acc[2] += f.x; acc[3] += f.y;
}

__global__ __launch_bounds__(256) void gather_kernel(float* __restrict__ out) {
    int node = (blockIdx.x * blockDim.x + threadIdx.x) >> 5;
    int lane = threadIdx.x & 31;
    if (node >= NNODES) return;

    int cnt = g_cnt[node];
    if (lane == 0) g_cnt[node] = 0;     // restore zero invariant
    int e = min(cnt, PAD);

    float acc[4];
    #pragma unroll
    for (int c = 0; c < 4; c++) acc[c] = 0.f;

    const size_t loff = (size_t)lane * 4;   // half offset within row
    const int* prow = &g_pad[node * PAD];

    int i = 0;
    for (; i + 7 < e; i += 8) {
        int sn[8];
        #pragma unroll
        for (int q = 0; q < 8; q++) sn[q] = __ldg(&prow[i + q]);
        uint2 v[8];
        #pragma unroll
        for (int q = 0; q < 8; q++)
            v[q] = *reinterpret_cast<const uint2*>(&g_y[(size_t)sn[q] * OUT_C + loff]);
        #pragma unroll
        for (int q = 0; q < 8; q++) acc_row4(acc, v[q]);
    }
    for (; i + 3 < e; i += 4) {
        int sn[4];
        #pragma unroll
        for (int q = 0; q < 4; q++) sn[q] = __ldg(&prow[i + q]);
        uint2 v[4];
        #pragma unroll
        for (int q = 0; q < 4; q++)
            v[q] = *reinterpret_cast<const uint2*>(&g_y[(size_t)sn[q] * OUT_C + loff]);
        #pragma unroll
        for (int q = 0; q < 4; q++) acc_row4(acc, v[q]);
    }
    for (; i < e; i++) {
        int s0 = __ldg(&prow[i]);
        uint2 v = *reinterpret_cast<const uint2*>(&g_y[(size_t)s0 * OUT_C + loff]);
        acc_row4(acc, v);
    }

    float inv = 1.0f / (float)max(cnt, 1);
    float4 o = make_float4(acc[0] * inv, acc[1] * inv, acc[2] * inv, acc[3] * inv);
    *reinterpret_cast<float4*>(&out[(size_t)node * OUT_C + loff]) = o;
}

// ---------------------------------------------------------------------------
extern "C" void kernel_launch(void* const* d_in, const int* in_sizes, int n_in,
                              void* d_out, int out_size) {
    const float* x  = (const float*)d_in[0];
    const int*   ei = (const int*)d_in[1];
    const float* W  = (const float*)d_in[2];
    const float* b  = (const float*)d_in[3];
    float* out = (float*)d_out;

    static cudaStream_t s_gemm = nullptr;
    static cudaEvent_t ev_fork = nullptr, ev_join = nullptr;
    if (!s_gemm) {
        cudaStreamCreateWithFlags(&s_gemm, cudaStreamNonBlocking);
        cudaEventCreateWithFlags(&ev_fork, cudaEventDisableTiming);
        cudaEventCreateWithFlags(&ev_join, cudaEventDisableTiming);
    }

    int edge_blocks4 = (NEDGES / 4 + 255) / 256;   // 4 edges per thread

    // Fork: GEMM on side stream (independent of bucket build)
    cudaEventRecord(ev_fork, 0);
    cudaStreamWaitEvent(s_gemm, ev_fork, 0);
    gemm_tf32_kernel<<<(NNODES + GBM - 1) / GBM, 256, 0, s_gemm>>>(x, W, b);
    cudaEventRecord(ev_join, s_gemm);

    // One-kernel bucket build on main stream (g_cnt is zero at entry)
    build_kernel<<<edge_blocks4, 256>>>(ei);

    // Join, then gather + mean (warp per node)
    cudaStreamWaitEvent(0, ev_join, 0);
    gather_kernel<<<(NNODES * 32 + 255) / 256, 256>>>(out);
}

// round 13
// speedup vs baseline: 1.6262x; 1.6262x over previous
#include <cuda_runtime.h>
#include <cuda_fp16.h>
#include <cstdint>

// Problem constants
#define NNODES 50000
#define NEDGES 800000
#define IN_C   256
#define OUT_C  128
#define NB3    25            // scan blocks: 25 * 2048 = 51200 >= NNODES

// Scratch
__device__ __align__(16) __half g_y[NNODES * OUT_C];  // linear output, fp16
__device__ __align__(16) int g_deg[NNODES];           // zero at entry (consumer-reset)
__device__ __align__(16) int g_off[NNODES + 1];
__device__ __align__(16) int g_rank[NEDGES];          // rank of edge within dst bucket
__device__ int g_srcs[NEDGES];
// decoupled-lookback scan state; zero at entry (fill resets after scan)
__device__ int g_blk_state[NB3];   // 0=invalid, 1=aggregate ready, 2=prefix ready
__device__ int g_blk_agg[NB3];
__device__ int g_blk_pref[NB3];

// ---------------------------------------------------------------------------
// K1: rank kernel — THE single atomic pass. 4 edges/thread via int4.
// ---------------------------------------------------------------------------
__global__ __launch_bounds__(256) void rank_kernel(const int* __restrict__ ei) {
    int t = blockIdx.x * blockDim.x + threadIdx.x;
    int base = t * 4;
    if (base >= NEDGES) return;
    int4 d = *reinterpret_cast<const int4*>(ei + NEDGES + base);
    int4 r;
    r.x = atomicAdd(&g_deg[d.x], 1);
    r.y = atomicAdd(&g_deg[d.y], 1);
    r.z = atomicAdd(&g_deg[d.z], 1);
    r.w = atomicAdd(&g_deg[d.w], 1);
    *reinterpret_cast<int4*>(&g_rank[base]) = r;
}

// ---------------------------------------------------------------------------
// K2: single-pass exclusive scan, warp-parallel decoupled lookback.
// 256 threads x 8 elements = 2048 per block, 25 blocks.
// Also resets g_deg to zero.
// ---------------------------------------------------------------------------
__global__ __launch_bounds__(256) void scan_lookback_kernel() {
    __shared__ int ws[8];
    __shared__ int s_excl;
    const int b = blockIdx.x;
    const int tid = threadIdx.x;
    const int lane = tid & 31, wid = tid >> 5;
    const int e0 = (b * 256 + tid) * 8;
    const bool inb0 = (e0 < NNODES);

    int4 da = inb0 ? *reinterpret_cast<const int4*>(&g_deg[e0])
                   : make_int4(0, 0, 0, 0);
    int4 db = inb0 ? *reinterpret_cast<const int4*>(&g_deg[e0 + 4])
                   : make_int4(0, 0, 0, 0);
    if (inb0) {
        *reinterpret_cast<int4*>(&g_deg[e0]) = make_int4(0, 0, 0, 0);
        *reinterpret_cast<int4*>(&g_deg[e0 + 4]) = make_int4(0, 0, 0, 0);
    }
    int p0 = da.x;
    int p1 = p0 + da.y;
    int p2 = p1 + da.z;
    int p3 = p2 + da.w;
    int p4 = p3 + db.x;
    int p5 = p4 + db.y;
    int p6 = p5 + db.z;
    int p7 = p6 + db.w;

    int incl = p7;
    #pragma unroll
    for (int dd = 1; dd < 32; dd <<= 1) {
        int u = __shfl_up_sync(0xffffffffu, incl, dd);
        if (lane >= dd) incl += u;
    }
    if (lane == 31) ws[wid] = incl;
    __syncthreads();
    if (wid == 0) {
        int s = (lane < 8) ? ws[lane] : 0;
        #pragma unroll
        for (int dd = 1; dd < 8; dd <<= 1) {
            int u = __shfl_up_sync(0xffffffffu, s, dd);
            if (lane >= dd) s += u;
        }
        if (lane < 8) ws[lane] = s;
    }
    __syncthreads();
    int thr_excl = incl - p7 + (wid > 0 ? ws[wid - 1] : 0);
    int total = ws[7];

    if (tid == 0) {
        if (b == 0) {
            g_blk_pref[0] = total;
            __threadfence();
            atomicExch(&g_blk_state[0], 2);
        } else {
            g_blk_agg[b] = total;
            __threadfence();
            atomicExch(&g_blk_state[b], 1);
        }
    }
    if (wid == 0) {
        int excl = 0;
        if (b > 0) {
            int hi_end = b;
            while (hi_end > 0) {
                int start = hi_end - 32 > 0 ? hi_end - 32 : 0;
                int idx = start + lane;
                bool valid = (idx < hi_end);
                int st = 2;
                do {
                    if (valid) st = atomicAdd(&g_blk_state[idx], 0);
                } while (__any_sync(0xffffffffu, valid && st == 0));
                int val = 0;
                if (valid)
                    val = (st == 2) ? atomicAdd(&g_blk_pref[idx], 0)
                                    : atomicAdd(&g_blk_agg[idx], 0);
                unsigned m2 = __ballot_sync(0xffffffffu, valid && st == 2);
                int contrib;
                bool done;
                if (m2) {
                    int hi = 31 - __clz(m2);
                    contrib = (valid && lane >= hi) ? val : 0;
                    done = true;
                } else {
                    contrib = valid ? val : 0;
                    done = false;
                }
                #pragma unroll
                for (int dd = 16; dd > 0; dd >>= 1)
                    contrib += __shfl_down_sync(0xffffffffu, contrib, dd);
                excl += __shfl_sync(0xffffffffu, contrib, 0);
                if (done) break;
                hi_end = start;
            }
            if (lane == 0) {
                g_blk_pref[b] = excl + total;
                __threadfence();
                atomicExch(&g_blk_state[b], 2);
            }
        }
        if (lane == 0) s_excl = excl;
    }
    __syncthreads();

    if (inb0) {
        int base = s_excl + thr_excl;
        int4 oa = make_int4(base, base + p0, base + p1, base + p2);
        int4 ob = make_int4(base + p3, base + p4, base + p5, base + p6);
        *reinterpret_cast<int4*>(&g_off[e0]) = oa;
        *reinterpret_cast<int4*>(&g_off[e0 + 4]) = ob;
    }
    if (b == 0 && tid == 0) g_off[NNODES] = NEDGES;
}

// ---------------------------------------------------------------------------
// K3: fill — NO atomics. pos = off[dst] + rank[e]. 4 edges/thread.
// Also resets the lookback state arrays.
// ---------------------------------------------------------------------------
__global__ __launch_bounds__(256) void fill_kernel(const int* __restrict__ ei) {
    int t = blockIdx.x * blockDim.x + threadIdx.x;
    if (t < NB3) g_blk_state[t] = 0;
    int base = t * 4;
    if (base >= NEDGES) return;
    int4 s = *reinterpret_cast<const int4*>(ei + base);
    int4 d = *reinterpret_cast<const int4*>(ei + NEDGES + base);
    int4 r = *reinterpret_cast<const int4*>(&g_rank[base]);
    int o0 = __ldg(&g_off[d.x]);
    int o1 = __ldg(&g_off[d.y]);
    int o2 = __ldg(&g_off[d.z]);
    int o3 = __ldg(&g_off[d.w]);
    g_srcs[o0 + r.x] = s.x;
    g_srcs[o1 + r.y] = s.y;
    g_srcs[o2 + r.z] = s.z;
    g_srcs[o3 + r.w] = s.w;
}

// ---------------------------------------------------------------------------
// K4: tf32 tensor-core GEMM, double-buffered smem, BM=64 for 3 CTAs/SM.
// y[m,n] = sum_k x[m,k] * W[n,k] + b[n], fp16 out.
// 8 warps in 4x2; warp tile 16x64 = 8 fragments of m16n8k8.
// ---------------------------------------------------------------------------
#define GBM 64
#define GBK 16
#define ASTRIDE 72    // 64 + 8; 72 mod 32 = 8 -> conflict-free fragment LDS
#define BSTRIDE 136   // 128 + 8
#define NTILES (IN_C / GBK)   // 16

__device__ __forceinline__ uint32_t f32_to_tf32(float f) {
    uint32_t r;
    asm("cvt.rna.tf32.f32 %0, %1;" : "=r"(r) : "f"(f));
    return r;
}

__global__ __launch_bounds__(256, 3) void gemm_tf32_kernel(
    const float* __restrict__ x,
    const float* __restrict__ W,
    const float* __restrict__ b)
{
    __shared__ uint32_t As[2][GBK * ASTRIDE];
    __shared__ uint32_t Bs[2][GBK * BSTRIDE];

    const int tid  = threadIdx.x;
    const int lane = tid & 31;
    const int warp = tid >> 5;
    const int wm   = warp >> 1;          // 0..3 -> m offset wm*16
    const int wn   = warp & 1;           // 0..1 -> n offset wn*64
    const int block_m = blockIdx.x * GBM;
    const int grp = lane >> 2;
    const int qid = lane & 3;

    // A load mapping: one float4 per thread per tile
    const int arow = tid >> 2;           // 0..63
    const int akq  = (tid & 3) * 4;      // 0,4,8,12
    const int gm   = block_m + arow;
    const bool aok = (gm < NNODES);
    // B load mapping: two float4 per thread per tile (rows 0..63, 64..127)
    const int brow0 = tid >> 2;
    const int bkq   = (tid & 3) * 4;

    float acc[8][4];
    #pragma unroll
    for (int j = 0; j < 8; j++)
        #pragma unroll
        for (int c = 0; c < 4; c++)
            acc[j][c] = 0.f;

    float4 pa, pb0, pb1;

    pa  = aok ? *reinterpret_cast<const float4*>(x + (size_t)gm * IN_C + akq)
              : make_float4(0.f, 0.f, 0.f, 0.f);
    pb0 = *reinterpret_cast<const float4*>(W + (size_t)brow0 * IN_C + bkq);
    pb1 = *reinterpret_cast<const float4*>(W + (size_t)(brow0 + 64) * IN_C + bkq);

    {
        As[0][(akq + 0) * ASTRIDE + arow] = f32_to_tf32(pa.x);
        As[0][(akq + 1) * ASTRIDE + arow] = f32_to_tf32(pa.y);
        As[0][(akq + 2) * ASTRIDE + arow] = f32_to_tf32(pa.z);
        As[0][(akq + 3) * ASTRIDE + arow] = f32_to_tf32(pa.w);
        Bs[0][(bkq + 0) * BSTRIDE + brow0] = f32_to_tf32(pb0.x);
        Bs[0][(bkq + 1) * BSTRIDE + brow0] = f32_to_tf32(pb0.y);
        Bs[0][(bkq + 2) * BSTRIDE + brow0] = f32_to_tf32(pb0.z);
        Bs[0][(bkq + 3) * BSTRIDE + brow0] = f32_to_tf32(pb0.w);
        Bs[0][(bkq + 0) * BSTRIDE + brow0 + 64] = f32_to_tf32(pb1.x);
        Bs[0][(bkq + 1) * BSTRIDE + brow0 + 64] = f32_to_tf32(pb1.y);
        Bs[0][(bkq + 2) * BSTRIDE + brow0 + 64] = f32_to_tf32(pb1.z);
        Bs[0][(bkq + 3) * BSTRIDE + brow0 + 64] = f32_to_tf32(pb1.w);
    }
    __syncthreads();

    for (int t = 0; t < NTILES; t++) {
        const int cur = t & 1;
        const bool has_next = (t + 1 < NTILES);

        if (has_next) {
            int k0 = (t + 1) * GBK;
            pa  = aok ? *reinterpret_cast<const float4*>(x + (size_t)gm * IN_C + k0 + akq)
                      : make_float4(0.f, 0.f, 0.f, 0.f);
            pb0 = *reinterpret_cast<const float4*>(W + (size_t)brow0 * IN_C + k0 + bkq);
            pb1 = *reinterpret_cast<const float4*>(W + (size_t)(brow0 + 64) * IN_C + k0 + bkq);
        }

        #pragma unroll
        for (int s = 0; s < 2; s++) {
            const int kk = s * 8 + qid;

            uint32_t af[4];
            {
                int rm = wm * 16 + grp;
                af[0] = As[cur][kk * ASTRIDE + rm];
                af[1] = As[cur][kk * ASTRIDE + rm + 8];
                af[2] = As[cur][(kk + 4) * ASTRIDE + rm];
                af[3] = As[cur][(kk + 4) * ASTRIDE + rm + 8];
            }
            uint32_t bf[8][2];
            #pragma unroll
            for (int j = 0; j < 8; j++) {
                int bn = wn * 64 + j * 8 + grp;
                bf[j][0] = Bs[cur][kk * BSTRIDE + bn];
                bf[j][1] = Bs[cur][(kk + 4) * BSTRIDE + bn];
            }
            #pragma unroll
            for (int j = 0; j < 8; j++) {
                asm volatile(
                    "mma.sync.aligned.m16n8k8.row.col.f32.tf32.tf32.f32 "
                    "{%0,%1,%2,%3}, {%4,%5,%6,%7}, {%8,%9}, {%0,%1,%2,%3};\n"
                    : "+f"(acc[j][0]), "+f"(acc[j][1]),
                      "+f"(acc[j][2]), "+f"(acc[j][3])
                    : "r"(af[0]), "r"(af[1]), "r"(af[2]), "r"(af[3]),
                      "r"(bf[j][0]), "r"(bf[j][1]));
            }
        }

        if (has_next) {
            const int nxt = cur ^ 1;
            As[nxt][(akq + 0) * ASTRIDE + arow] = f32_to_tf32(pa.x);
            As[nxt][(akq + 1) * ASTRIDE + arow] = f32_to_tf32(pa.y);
            As[nxt][(akq + 2) * ASTRIDE + arow] = f32_to_tf32(pa.z);
            As[nxt][(akq + 3) * ASTRIDE + arow] = f32_to_tf32(pa.w);
            Bs[nxt][(bkq + 0) * BSTRIDE + brow0] = f32_to_tf32(pb0.x);
            Bs[nxt][(bkq + 1) * BSTRIDE + brow0] = f32_to_tf32(pb0.y);
            Bs[nxt][(bkq + 2) * BSTRIDE + brow0] = f32_to_tf32(pb0.z);
            Bs[nxt][(bkq + 3) * BSTRIDE + brow0] = f32_to_tf32(pb0.w);
            Bs[nxt][(bkq + 0) * BSTRIDE + brow0 + 64] = f32_to_tf32(pb1.x);
            Bs[nxt][(bkq + 1) * BSTRIDE + brow0 + 64] = f32_to_tf32(pb1.y);
            Bs[nxt][(bkq + 2) * BSTRIDE + brow0 + 64] = f32_to_tf32(pb1.z);
            Bs[nxt][(bkq + 3) * BSTRIDE + brow0 + 64] = f32_to_tf32(pb1.w);
            __syncthreads();
        }
    }

    // Epilogue: bias + fp16 store
    {
        int r0 = block_m + wm * 16 + grp;
        int r1 = r0 + 8;
        #pragma unroll
        for (int j = 0; j < 8; j++) {
            int col = wn * 64 + j * 8 + qid * 2;
            float b0 = b[col], b1 = b[col + 1];
            if (r0 < NNODES) {
                __half2 h = __floats2half2_rn(acc[j][0] + b0, acc[j][1] + b1);
                *reinterpret_cast<__half2*>(&g_y[(size_t)r0 * OUT_C + col]) = h;
            }
            if (r1 < NNODES) {
                __half2 h = __floats2half2_rn(acc[j][2] + b0, acc[j][3] + b1);
                *reinterpret_cast<__half2*>(&g_y[(size_t)r1 * OUT_C + col]) = h;
            }
        }
    }
}

// ---------------------------------------------------------------------------
// K5: gather + mean. 2 nodes per warp; 16 lanes per node; one uint4 (8 halfs)
// per lane. fp32 accumulation, unrolled x8 for MLP.
// ---------------------------------------------------------------------------
__device__ __forceinline__ void acc_row(float* acc, uint4 v) {
    float2 f;
    f = __half22float2(*reinterpret_cast<__half2*>(&v.x)); acc[0] += f.x; acc[1] += f.y;
    f = __half22float2(*reinterpret_cast<__half2*>(&v.y)); acc[2] += f.x; acc[3] += f.y;
    f = __half22float2(*reinterpret_cast<__half2*>(&v.z)); acc[4] += f.x; acc[5] += f.y;
    f = __half22float2(*reinterpret_cast<__half2*>(&v.w)); acc[6] += f.x; acc[7] += f.y;
}

__global__ __launch_bounds__(256) void gather_kernel(float* __restrict__ out) {
    int warp_id = (blockIdx.x * blockDim.x + threadIdx.x) >> 5;
    int lane = threadIdx.x & 31;
    int half_id = lane >> 4;
    int sub = lane & 15;
    int node = warp_id * 2 + half_id;
    if (node >= NNODES) return;

    int s = g_off[node];
    int e = g_off[node + 1];

    float acc[8];
    #pragma unroll
    for (int c = 0; c < 8; c++) acc[c] = 0.f;

    const size_t loff = (size_t)sub * 8;

    int i = s;
    for (; i + 7 < e; i += 8) {
        int sn[8];
        #pragma unroll
        for (int q = 0; q < 8; q++) sn[q] = __ldg(&g_srcs[i + q]);
        uint4 v[8];
        #pragma unroll
        for (int q = 0; q < 8; q++)
            v[q] = *reinterpret_cast<const uint4*>(&g_y[(size_t)sn[q] * OUT_C + loff]);
        #pragma unroll
        for (int q = 0; q < 8; q++) acc_row(acc, v[q]);
    }
    for (; i + 3 < e; i += 4) {
        int sn[4];
        #pragma unroll
        for (int q = 0; q < 4; q++) sn[q] = __ldg(&g_srcs[i + q]);
        uint4 v[4];
        #pragma unroll
        for (int q = 0; q < 4; q++)
            v[q] = *reinterpret_cast<const uint4*>(&g_y[(size_t)sn[q] * OUT_C + loff]);
        #pragma unroll
        for (int q = 0; q < 4; q++) acc_row(acc, v[q]);
    }
    for (; i < e; i++) {
        int s0 = __ldg(&g_srcs[i]);
        uint4 v = *reinterpret_cast<const uint4*>(&g_y[(size_t)s0 * OUT_C + loff]);
        acc_row(acc, v);
    }

    float inv = 1.0f / (float)max(e - s, 1);
    float4 o0 = make_float4(acc[0] * inv, acc[1] * inv, acc[2] * inv, acc[3] * inv);
    float4 o1 = make_float4(acc[4] * inv, acc[5] * inv, acc[6] * inv, acc[7] * inv);
    float* op = out + (size_t)node * OUT_C + loff;
    *reinterpret_cast<float4*>(op) = o0;
    *reinterpret_cast<float4*>(op + 4) = o1;
}

// ---------------------------------------------------------------------------
extern "C" void kernel_launch(void* const* d_in, const int* in_sizes, int n_in,
                              void* d_out, int out_size) {
    const float* x  = (const float*)d_in[0];
    const int*   ei = (const int*)d_in[1];
    const float* W  = (const float*)d_in[2];
    const float* b  = (const float*)d_in[3];
    float* out = (float*)d_out;

    static cudaStream_t s_gemm = nullptr;
    static cudaEvent_t ev_fork = nullptr, ev_join = nullptr;
    if (!s_gemm) {
        cudaStreamCreateWithFlags(&s_gemm, cudaStreamNonBlocking);
        cudaEventCreateWithFlags(&ev_fork, cudaEventDisableTiming);
        cudaEventCreateWithFlags(&ev_join, cudaEventDisableTiming);
    }

    int edge_blocks4 = (NEDGES / 4 + 255) / 256;   // 4 edges per thread

    // Fork: GEMM on side stream (independent of CSR build)
    cudaEventRecord(ev_fork, 0);
    cudaStreamWaitEvent(s_gemm, ev_fork, 0);
    gemm_tf32_kernel<<<(NNODES + GBM - 1) / GBM, 256, 0, s_gemm>>>(x, W, b);
    cudaEventRecord(ev_join, s_gemm);

    // CSR build on main stream (g_deg, g_blk_state are zero at entry)
    rank_kernel<<<edge_blocks4, 256>>>(ei);
    scan_lookback_kernel<<<NB3, 256>>>();
    fill_kernel<<<edge_blocks4, 256>>>(ei);

    // Join, then gather + mean
    cudaStreamWaitEvent(0, ev_join, 0);
    gather_kernel<<<(NNODES / 2 * 32 + 255) / 256, 256>>>(out);
}

// round 14
// speedup vs baseline: 1.9533x; 1.2011x over previous
#include <cuda_runtime.h>
#include <cuda_fp16.h>
#include <cstdint>

// Problem constants
#define NNODES 50000
#define NEDGES 800000
#define IN_C   256
#define OUT_C  128
#define NB3    25            // scan blocks: 25 * 2048 = 51200 >= NNODES

// Scratch
__device__ __align__(16) __half g_y[NNODES * OUT_C];  // linear output, fp16
__device__ __align__(16) int g_deg[NNODES];           // zero at entry (consumer-reset)
__device__ __align__(16) int g_off[NNODES + 1];
__device__ __align__(16) int g_rank[NEDGES];          // rank of edge within dst bucket
__device__ int g_srcs[NEDGES];
// decoupled-lookback scan state; zero at entry (fill resets after scan)
__device__ int g_blk_state[NB3];
__device__ int g_blk_agg[NB3];
__device__ int g_blk_pref[NB3];

// ---------------------------------------------------------------------------
// K1: rank kernel — THE single atomic pass. 4 edges/thread via int4.
// ---------------------------------------------------------------------------
__global__ __launch_bounds__(256) void rank_kernel(const int* __restrict__ ei) {
    int t = blockIdx.x * blockDim.x + threadIdx.x;
    int base = t * 4;
    if (base >= NEDGES) return;
    int4 d = *reinterpret_cast<const int4*>(ei + NEDGES + base);
    int4 r;
    r.x = atomicAdd(&g_deg[d.x], 1);
    r.y = atomicAdd(&g_deg[d.y], 1);
    r.z = atomicAdd(&g_deg[d.z], 1);
    r.w = atomicAdd(&g_deg[d.w], 1);
    *reinterpret_cast<int4*>(&g_rank[base]) = r;
}

// ---------------------------------------------------------------------------
// K2: single-pass exclusive scan, warp-parallel decoupled lookback.
// 256 threads x 8 elements = 2048 per block, 25 blocks. Resets g_deg.
// ---------------------------------------------------------------------------
__global__ __launch_bounds__(256) void scan_lookback_kernel() {
    __shared__ int ws[8];
    __shared__ int s_excl;
    const int b = blockIdx.x;
    const int tid = threadIdx.x;
    const int lane = tid & 31, wid = tid >> 5;
    const int e0 = (b * 256 + tid) * 8;
    const bool inb0 = (e0 < NNODES);

    int4 da = inb0 ? *reinterpret_cast<const int4*>(&g_deg[e0])
                   : make_int4(0, 0, 0, 0);
    int4 db = inb0 ? *reinterpret_cast<const int4*>(&g_deg[e0 + 4])
                   : make_int4(0, 0, 0, 0);
    if (inb0) {
        *reinterpret_cast<int4*>(&g_deg[e0]) = make_int4(0, 0, 0, 0);
        *reinterpret_cast<int4*>(&g_deg[e0 + 4]) = make_int4(0, 0, 0, 0);
    }
    int p0 = da.x;
    int p1 = p0 + da.y;
    int p2 = p1 + da.z;
    int p3 = p2 + da.w;
    int p4 = p3 + db.x;
    int p5 = p4 + db.y;
    int p6 = p5 + db.z;
    int p7 = p6 + db.w;

    int incl = p7;
    #pragma unroll
    for (int dd = 1; dd < 32; dd <<= 1) {
        int u = __shfl_up_sync(0xffffffffu, incl, dd);
        if (lane >= dd) incl += u;
    }
    if (lane == 31) ws[wid] = incl;
    __syncthreads();
    if (wid == 0) {
        int s = (lane < 8) ? ws[lane] : 0;
        #pragma unroll
        for (int dd = 1; dd < 8; dd <<= 1) {
            int u = __shfl_up_sync(0xffffffffu, s, dd);
            if (lane >= dd) s += u;
        }
        if (lane < 8) ws[lane] = s;
    }
    __syncthreads();
    int thr_excl = incl - p7 + (wid > 0 ? ws[wid - 1] : 0);
    int total = ws[7];

    if (tid == 0) {
        if (b == 0) {
            g_blk_pref[0] = total;
            __threadfence();
            atomicExch(&g_blk_state[0], 2);
        } else {
            g_blk_agg[b] = total;
            __threadfence();
            atomicExch(&g_blk_state[b], 1);
        }
    }
    if (wid == 0) {
        int excl = 0;
        if (b > 0) {
            int hi_end = b;
            while (hi_end > 0) {
                int start = hi_end - 32 > 0 ? hi_end - 32 : 0;
                int idx = start + lane;
                bool valid = (idx < hi_end);
                int st = 2;
                do {
                    if (valid) st = atomicAdd(&g_blk_state[idx], 0);
                } while (__any_sync(0xffffffffu, valid && st == 0));
                int val = 0;
                if (valid)
                    val = (st == 2) ? atomicAdd(&g_blk_pref[idx], 0)
                                    : atomicAdd(&g_blk_agg[idx], 0);
                unsigned m2 = __ballot_sync(0xffffffffu, valid && st == 2);
                int contrib;
                bool done;
                if (m2) {
                    int hi = 31 - __clz(m2);
                    contrib = (valid && lane >= hi) ? val : 0;
                    done = true;
                } else {
                    contrib = valid ? val : 0;
                    done = false;
                }
                #pragma unroll
                for (int dd = 16; dd > 0; dd >>= 1)
                    contrib += __shfl_down_sync(0xffffffffu, contrib, dd);
                excl += __shfl_sync(0xffffffffu, contrib, 0);
                if (done) break;
                hi_end = start;
            }
            if (lane == 0) {
                g_blk_pref[b] = excl + total;
                __threadfence();
                atomicExch(&g_blk_state[b], 2);
            }
        }
        if (lane == 0) s_excl = excl;
    }
    __syncthreads();

    if (inb0) {
        int base = s_excl + thr_excl;
        int4 oa = make_int4(base, base + p0, base + p1, base + p2);
        int4 ob = make_int4(base + p3, base + p4, base + p5, base + p6);
        *reinterpret_cast<int4*>(&g_off[e0]) = oa;
        *reinterpret_cast<int4*>(&g_off[e0 + 4]) = ob;
    }
    if (b == 0 && tid == 0) g_off[NNODES] = NEDGES;
}

// ---------------------------------------------------------------------------
// K3: fill — NO atomics. pos = off[dst] + rank[e]. 4 edges/thread.
// Also resets the lookback state arrays.
// ---------------------------------------------------------------------------
__global__ __launch_bounds__(256) void fill_kernel(const int* __restrict__ ei) {
    int t = blockIdx.x * blockDim.x + threadIdx.x;
    if (t < NB3) g_blk_state[t] = 0;
    int base = t * 4;
    if (base >= NEDGES) return;
    int4 s = *reinterpret_cast<const int4*>(ei + base);
    int4 d = *reinterpret_cast<const int4*>(ei + NEDGES + base);
    int4 r = *reinterpret_cast<const int4*>(&g_rank[base]);
    int o0 = __ldg(&g_off[d.x]);
    int o1 = __ldg(&g_off[d.y]);
    int o2 = __ldg(&g_off[d.z]);
    int o3 = __ldg(&g_off[d.w]);
    g_srcs[o0 + r.x] = s.x;
    g_srcs[o1 + r.y] = s.y;
    g_srcs[o2 + r.z] = s.z;
    g_srcs[o3 + r.w] = s.w;
}

// ---------------------------------------------------------------------------
// K4: fp16 tensor-core GEMM (m16n8k16, fp32 accum), double-buffered smem.
// y[m,n] = sum_k x[m,k] * W[n,k] + b[n], fp16 out.
// BM=128, BN=128, BK=16; 8 warps 4x2; warp tile 32x64.
// Smem word = half2 holding k-values (2k, 2k+1) for one m. Same padded
// addressing as the tf32 version (SSTRIDE=136 words).
// ---------------------------------------------------------------------------
#define GBM 128
#define GBK 16
#define SSTRIDE 136
#define NTILES (IN_C / GBK)   // 16

__device__ __forceinline__ uint32_t pack_h2(float a, float b) {
    __half2 h = __floats2half2_rn(a, b);
    return *reinterpret_cast<uint32_t*>(&h);
}

__global__ __launch_bounds__(256, 2) void gemm_fp16_kernel(
    const float* __restrict__ x,
    const float* __restrict__ W,
    const float* __restrict__ b)
{
    // 8 k2-rows per tile (BK=16 -> k2 = 0..7)
    __shared__ uint32_t As[2][8 * SSTRIDE];
    __shared__ uint32_t Bs[2][8 * SSTRIDE];

    const int tid  = threadIdx.x;
    const int lane = tid & 31;
    const int warp = tid >> 5;
    const int wm   = warp >> 1;
    const int wn   = warp & 1;
    const int block_m = blockIdx.x * GBM;
    const int grp = lane >> 2;
    const int qid = lane & 3;

    // load mapping: 2 float4 per thread per tile; idx -> (row, kq)
    const int idx0 = tid * 2;
    const int row0 = idx0 >> 2;             // 0..127
    const int kq0  = (idx0 & 3) * 4;        // 0,4,8,12
    const int row1 = (idx0 + 1) >> 2;
    const int kq1  = ((idx0 + 1) & 3) * 4;
    const int gm0 = block_m + row0;
    const int gm1 = block_m + row1;
    const bool ok0 = (gm0 < NNODES);
    const bool ok1 = (gm1 < NNODES);

    float acc[2][8][4];
    #pragma unroll
    for (int i = 0; i < 2; i++)
        #pragma unroll
        for (int j = 0; j < 8; j++)
            #pragma unroll
            for (int c = 0; c < 4; c++)
                acc[i][j][c] = 0.f;

    float4 pa0, pa1, pb0, pb1;

    pa0 = ok0 ? *reinterpret_cast<const float4*>(x + (size_t)gm0 * IN_C + kq0)
              : make_float4(0.f, 0.f, 0.f, 0.f);
    pa1 = ok1 ? *reinterpret_cast<const float4*>(x + (size_t)gm1 * IN_C + kq1)
              : make_float4(0.f, 0.f, 0.f, 0.f);
    pb0 = *reinterpret_cast<const float4*>(W + (size_t)row0 * IN_C + kq0);
    pb1 = *reinterpret_cast<const float4*>(W + (size_t)row1 * IN_C + kq1);

    {
        // kq/2 in {0,2,4,6}; each float4 -> two half2 words
        As[0][((kq0 >> 1) + 0) * SSTRIDE + row0] = pack_h2(pa0.x, pa0.y);
        As[0][((kq0 >> 1) + 1) * SSTRIDE + row0] = pack_h2(pa0.z, pa0.w);
        As[0][((kq1 >> 1) + 0) * SSTRIDE + row1] = pack_h2(pa1.x, pa1.y);
        As[0][((kq1 >> 1) + 1) * SSTRIDE + row1] = pack_h2(pa1.z, pa1.w);
        Bs[0][((kq0 >> 1) + 0) * SSTRIDE + row0] = pack_h2(pb0.x, pb0.y);
        Bs[0][((kq0 >> 1) + 1) * SSTRIDE + row0] = pack_h2(pb0.z, pb0.w);
        Bs[0][((kq1 >> 1) + 0) * SSTRIDE + row1] = pack_h2(pb1.x, pb1.y);
        Bs[0][((kq1 >> 1) + 1) * SSTRIDE + row1] = pack_h2(pb1.z, pb1.w);
    }
    __syncthreads();

    for (int t = 0; t < NTILES; t++) {
        const int cur = t & 1;
        const bool has_next = (t + 1 < NTILES);

        if (has_next) {
            int k0 = (t + 1) * GBK;
            pa0 = ok0 ? *reinterpret_cast<const float4*>(x + (size_t)gm0 * IN_C + k0 + kq0)
                      : make_float4(0.f, 0.f, 0.f, 0.f);
            pa1 = ok1 ? *reinterpret_cast<const float4*>(x + (size_t)gm1 * IN_C + k0 + kq1)
                      : make_float4(0.f, 0.f, 0.f, 0.f);
            pb0 = *reinterpret_cast<const float4*>(W + (size_t)row0 * IN_C + k0 + kq0);
            pb1 = *reinterpret_cast<const float4*>(W + (size_t)row1 * IN_C + k0 + kq1);
        }

        // one m16n8k16 step covers the whole BK=16 tile (k2 = 0..7)
        {
            uint32_t af[2][4];
            #pragma unroll
            for (int i = 0; i < 2; i++) {
                int rm = wm * 32 + i * 16 + grp;
                af[i][0] = As[cur][qid * SSTRIDE + rm];          // k2 = qid
                af[i][1] = As[cur][qid * SSTRIDE + rm + 8];
                af[i][2] = As[cur][(qid + 4) * SSTRIDE + rm];    // k2 = qid+4
                af[i][3] = As[cur][(qid + 4) * SSTRIDE + rm + 8];
            }
            uint32_t bf[8][2];
            #pragma unroll
            for (int j = 0; j < 8; j++) {
                int bn = wn * 64 + j * 8 + grp;
                bf[j][0] = Bs[cur][qid * SSTRIDE + bn];
                bf[j][1] = Bs[cur][(qid + 4) * SSTRIDE + bn];
            }
            #pragma unroll
            for (int i = 0; i < 2; i++)
                #pragma unroll
                for (int j = 0; j < 8; j++) {
                    asm volatile(
                        "mma.sync.aligned.m16n8k16.row.col.f32.f16.f16.f32 "
                        "{%0,%1,%2,%3}, {%4,%5,%6,%7}, {%8,%9}, {%0,%1,%2,%3};\n"
                        : "+f"(acc[i][j][0]), "+f"(acc[i][j][1]),
                          "+f"(acc[i][j][2]), "+f"(acc[i][j][3])
                        : "r"(af[i][0]), "r"(af[i][1]), "r"(af[i][2]), "r"(af[i][3]),
                          "r"(bf[j][0]), "r"(bf[j][1]));
                }
        }

        if (has_next) {
            const int nxt = cur ^ 1;
            As[nxt][((kq0 >> 1) + 0) * SSTRIDE + row0] = pack_h2(pa0.x, pa0.y);
            As[nxt][((kq0 >> 1) + 1) * SSTRIDE + row0] = pack_h2(pa0.z, pa0.w);
            As[nxt][((kq1 >> 1) + 0) * SSTRIDE + row1] = pack_h2(pa1.x, pa1.y);
            As[nxt][((kq1 >> 1) + 1) * SSTRIDE + row1] = pack_h2(pa1.z, pa1.w);
            Bs[nxt][((kq0 >> 1) + 0) * SSTRIDE + row0] = pack_h2(pb0.x, pb0.y);
            Bs[nxt][((kq0 >> 1) + 1) * SSTRIDE + row0] = pack_h2(pb0.z, pb0.w);
            Bs[nxt][((kq1 >> 1) + 0) * SSTRIDE + row1] = pack_h2(pb1.x, pb1.y);
            Bs[nxt][((kq1 >> 1) + 1) * SSTRIDE + row1] = pack_h2(pb1.z, pb1.w);
            __syncthreads();
        }
    }

    // Epilogue: bias + fp16 store (accumulator fragment layout same as k8)
    #pragma unroll
    for (int i = 0; i < 2; i++) {
        int r0 = block_m + wm * 32 + i * 16 + grp;
        int r1 = r0 + 8;
        #pragma unroll
        for (int j = 0; j < 8; j++) {
            int col = wn * 64 + j * 8 + qid * 2;
            float b0 = b[col], b1 = b[col + 1];
            if (r0 < NNODES) {
                __half2 h = __floats2half2_rn(acc[i][j][0] + b0, acc[i][j][1] + b1);
                *reinterpret_cast<__half2*>(&g_y[(size_t)r0 * OUT_C + col]) = h;
            }
            if (r1 < NNODES) {
                __half2 h = __floats2half2_rn(acc[i][j][2] + b0, acc[i][j][3] + b1);
                *reinterpret_cast<__half2*>(&g_y[(size_t)r1 * OUT_C + col]) = h;
            }
        }
    }
}

// ---------------------------------------------------------------------------
// K5: gather + mean. 2 nodes per warp; 16 lanes per node; one uint4 (8 halfs)
// per lane. fp32 accumulation, unrolled x8 for MLP.
// ---------------------------------------------------------------------------
__device__ __forceinline__ void acc_row(float* acc, uint4 v) {
    float2 f;
    f = __half22float2(*reinterpret_cast<__half2*>(&v.x)); acc[0] += f.x; acc[1] += f.y;
    f = __half22float2(*reinterpret_cast<__half2*>(&v.y)); acc[2] += f.x; acc[3] += f.y;
    f = __half22float2(*reinterpret_cast<__half2*>(&v.z)); acc[4] += f.x; acc[5] += f.y;
    f = __half22float2(*reinterpret_cast<__half2*>(&v.w)); acc[6] += f.x; acc[7] += f.y;
}

__global__ __launch_bounds__(256) void gather_kernel(float* __restrict__ out) {
    int warp_id = (blockIdx.x * blockDim.x + threadIdx.x) >> 5;
    int lane = threadIdx.x & 31;
    int half_id = lane >> 4;
    int sub = lane & 15;
    int node = warp_id * 2 + half_id;
    if (node >= NNODES) return;

    int s = g_off[node];
    int e = g_off[node + 1];

    float acc[8];
    #pragma unroll
    for (int c = 0; c < 8; c++) acc[c] = 0.f;

    const size_t loff = (size_t)sub * 8;

    int i = s;
    for (; i + 7 < e; i += 8) {
        int sn[8];
        #pragma unroll
        for (int q = 0; q < 8; q++) sn[q] = __ldg(&g_srcs[i + q]);
        uint4 v[8];
        #pragma unroll
        for (int q = 0; q < 8; q++)
            v[q] = *reinterpret_cast<const uint4*>(&g_y[(size_t)sn[q] * OUT_C + loff]);
        #pragma unroll
        for (int q = 0; q < 8; q++) acc_row(acc, v[q]);
    }
    for (; i + 3 < e; i += 4) {
        int sn[4];
        #pragma unroll
        for (int q = 0; q < 4; q++) sn[q] = __ldg(&g_srcs[i + q]);
        uint4 v[4];
        #pragma unroll
        for (int q = 0; q < 4; q++)
            v[q] = *reinterpret_cast<const uint4*>(&g_y[(size_t)sn[q] * OUT_C + loff]);
        #pragma unroll
        for (int q = 0; q < 4; q++) acc_row(acc, v[q]);
    }
    for (; i < e; i++) {
        int s0 = __ldg(&g_srcs[i]);
        uint4 v = *reinterpret_cast<const uint4*>(&g_y[(size_t)s0 * OUT_C + loff]);
        acc_row(acc, v);
    }

    float inv = 1.0f / (float)max(e - s, 1);
    float4 o0 = make_float4(acc[0] * inv, acc[1] * inv, acc[2] * inv, acc[3] * inv);
    float4 o1 = make_float4(acc[4] * inv, acc[5] * inv, acc[6] * inv, acc[7] * inv);
    float* op = out + (size_t)node * OUT_C + loff;
    *reinterpret_cast<float4*>(op) = o0;
    *reinterpret_cast<float4*>(op + 4) = o1;
}

// ---------------------------------------------------------------------------
extern "C" void kernel_launch(void* const* d_in, const int* in_sizes, int n_in,
                              void* d_out, int out_size) {
    const float* x  = (const float*)d_in[0];
    const int*   ei = (const int*)d_in[1];
    const float* W  = (const float*)d_in[2];
    const float* b  = (const float*)d_in[3];
    float* out = (float*)d_out;

    static cudaStream_t s_gemm = nullptr;
    static cudaEvent_t ev_fork = nullptr, ev_join = nullptr;
    if (!s_gemm) {
        cudaStreamCreateWithFlags(&s_gemm, cudaStreamNonBlocking);
        cudaEventCreateWithFlags(&ev_fork, cudaEventDisableTiming);
        cudaEventCreateWithFlags(&ev_join, cudaEventDisableTiming);
    }

    int edge_blocks4 = (NEDGES / 4 + 255) / 256;   // 4 edges per thread

    // Fork: GEMM on side stream (independent of CSR build)
    cudaEventRecord(ev_fork, 0);
    cudaStreamWaitEvent(s_gemm, ev_fork, 0);
    gemm_fp16_kernel<<<(NNODES + GBM - 1) / GBM, 256, 0, s_gemm>>>(x, W, b);
    cudaEventRecord(ev_join, s_gemm);

    // CSR build on main stream (g_deg, g_blk_state are zero at entry)
    rank_kernel<<<edge_blocks4, 256>>>(ei);
    scan_lookback_kernel<<<NB3, 256>>>();
    fill_kernel<<<edge_blocks4, 256>>>(ei);

    // Join, then gather + mean
    cudaStreamWaitEvent(0, ev_join, 0);
    gather_kernel<<<(NNODES / 2 * 32 + 255) / 256, 256>>>(out);
}

// round 15
// speedup vs baseline: 1.9857x; 1.0166x over previous
#include <cuda_runtime.h>
#include <cuda_fp16.h>
#include <cstdint>

// Problem constants
#define NNODES 50000
#define NEDGES 800000
#define IN_C   256
#define OUT_C  128
#define NB3    25            // scan blocks: 25 * 2048 = 51200 >= NNODES

// Scratch
__device__ __align__(16) __half g_y[NNODES * OUT_C];  // linear output, fp16
__device__ __align__(16) int g_deg[NNODES];           // zero at entry (consumer-reset)
__device__ __align__(16) int g_off[NNODES + 1];
__device__ __align__(16) int g_rank[NEDGES];          // rank of edge within dst bucket
__device__ int g_srcs[NEDGES];
// decoupled-lookback scan state; zero at entry (fill resets after scan)
__device__ int g_blk_state[NB3];
__device__ int g_blk_agg[NB3];
__device__ int g_blk_pref[NB3];

// ---------------------------------------------------------------------------
// K1: rank kernel — THE single atomic pass. 4 edges/thread via int4.
// ---------------------------------------------------------------------------
__global__ __launch_bounds__(256) void rank_kernel(const int* __restrict__ ei) {
    int t = blockIdx.x * blockDim.x + threadIdx.x;
    int base = t * 4;
    if (base >= NEDGES) return;
    int4 d = *reinterpret_cast<const int4*>(ei + NEDGES + base);
    int4 r;
    r.x = atomicAdd(&g_deg[d.x], 1);
    r.y = atomicAdd(&g_deg[d.y], 1);
    r.z = atomicAdd(&g_deg[d.z], 1);
    r.w = atomicAdd(&g_deg[d.w], 1);
    *reinterpret_cast<int4*>(&g_rank[base]) = r;
}

// ---------------------------------------------------------------------------
// K2: single-pass exclusive scan, warp-parallel decoupled lookback.
// 256 threads x 8 elements = 2048 per block, 25 blocks. Resets g_deg.
// ---------------------------------------------------------------------------
__global__ __launch_bounds__(256) void scan_lookback_kernel() {
    __shared__ int ws[8];
    __shared__ int s_excl;
    const int b = blockIdx.x;
    const int tid = threadIdx.x;
    const int lane = tid & 31, wid = tid >> 5;
    const int e0 = (b * 256 + tid) * 8;
    const bool inb0 = (e0 < NNODES);

    int4 da = inb0 ? *reinterpret_cast<const int4*>(&g_deg[e0])
                   : make_int4(0, 0, 0, 0);
    int4 db = inb0 ? *reinterpret_cast<const int4*>(&g_deg[e0 + 4])
                   : make_int4(0, 0, 0, 0);
    if (inb0) {
        *reinterpret_cast<int4*>(&g_deg[e0]) = make_int4(0, 0, 0, 0);
        *reinterpret_cast<int4*>(&g_deg[e0 + 4]) = make_int4(0, 0, 0, 0);
    }
    int p0 = da.x;
    int p1 = p0 + da.y;
    int p2 = p1 + da.z;
    int p3 = p2 + da.w;
    int p4 = p3 + db.x;
    int p5 = p4 + db.y;
    int p6 = p5 + db.z;
    int p7 = p6 + db.w;

    int incl = p7;
    #pragma unroll
    for (int dd = 1; dd < 32; dd <<= 1) {
        int u = __shfl_up_sync(0xffffffffu, incl, dd);
        if (lane >= dd) incl += u;
    }
    if (lane == 31) ws[wid] = incl;
    __syncthreads();
    if (wid == 0) {
        int s = (lane < 8) ? ws[lane] : 0;
        #pragma unroll
        for (int dd = 1; dd < 8; dd <<= 1) {
            int u = __shfl_up_sync(0xffffffffu, s, dd);
            if (lane >= dd) s += u;
        }
        if (lane < 8) ws[lane] = s;
    }
    __syncthreads();
    int thr_excl = incl - p7 + (wid > 0 ? ws[wid - 1] : 0);
    int total = ws[7];

    if (tid == 0) {
        if (b == 0) {
            g_blk_pref[0] = total;
            __threadfence();
            atomicExch(&g_blk_state[0], 2);
        } else {
            g_blk_agg[b] = total;
            __threadfence();
            atomicExch(&g_blk_state[b], 1);
        }
    }
    if (wid == 0) {
        int excl = 0;
        if (b > 0) {
            int hi_end = b;
            while (hi_end > 0) {
                int start = hi_end - 32 > 0 ? hi_end - 32 : 0;
                int idx = start + lane;
                bool valid = (idx < hi_end);
                int st = 2;
                do {
                    if (valid) st = atomicAdd(&g_blk_state[idx], 0);
                } while (__any_sync(0xffffffffu, valid && st == 0));
                int val = 0;
                if (valid)
                    val = (st == 2) ? atomicAdd(&g_blk_pref[idx], 0)
                                    : atomicAdd(&g_blk_agg[idx], 0);
                unsigned m2 = __ballot_sync(0xffffffffu, valid && st == 2);
                int contrib;
                bool done;
                if (m2) {
                    int hi = 31 - __clz(m2);
                    contrib = (valid && lane >= hi) ? val : 0;
                    done = true;
                } else {
                    contrib = valid ? val : 0;
                    done = false;
                }
                #pragma unroll
                for (int dd = 16; dd > 0; dd >>= 1)
                    contrib += __shfl_down_sync(0xffffffffu, contrib, dd);
                excl += __shfl_sync(0xffffffffu, contrib, 0);
                if (done) break;
                hi_end = start;
            }
            if (lane == 0) {
                g_blk_pref[b] = excl + total;
                __threadfence();
                atomicExch(&g_blk_state[b], 2);
            }
        }
        if (lane == 0) s_excl = excl;
    }
    __syncthreads();

    if (inb0) {
        int base = s_excl + thr_excl;
        int4 oa = make_int4(base, base + p0, base + p1, base + p2);
        int4 ob = make_int4(base + p3, base + p4, base + p5, base + p6);
        *reinterpret_cast<int4*>(&g_off[e0]) = oa;
        *reinterpret_cast<int4*>(&g_off[e0 + 4]) = ob;
    }
    if (b == 0 && tid == 0) g_off[NNODES] = NEDGES;
}

// ---------------------------------------------------------------------------
// K3: fill — NO atomics. pos = off[dst] + rank[e]. 2 edges/thread for
// higher occupancy (1563 CTAs -> ~84%). Resets lookback state.
// ---------------------------------------------------------------------------
__global__ __launch_bounds__(256) void fill_kernel(const int* __restrict__ ei) {
    int t = blockIdx.x * blockDim.x + threadIdx.x;
    if (t < NB3) g_blk_state[t] = 0;
    int base = t * 2;
    if (base >= NEDGES) return;
    int2 s = *reinterpret_cast<const int2*>(ei + base);
    int2 d = *reinterpret_cast<const int2*>(ei + NEDGES + base);
    int2 r = *reinterpret_cast<const int2*>(&g_rank[base]);
    int o0 = __ldg(&g_off[d.x]);
    int o1 = __ldg(&g_off[d.y]);
    g_srcs[o0 + r.x] = s.x;
    g_srcs[o1 + r.y] = s.y;
}

// ---------------------------------------------------------------------------
// K4: fp16 tensor-core GEMM (m16n8k16, fp32 accum), double-buffered smem.
// y[m,n] = sum_k x[m,k] * W[n,k] + b[n], fp16 out.
// BM=128, BN=128, BK=16; 8 warps 4x2; warp tile 32x64.
// ---------------------------------------------------------------------------
#define GBM 128
#define GBK 16
#define SSTRIDE 136
#define NTILES (IN_C / GBK)   // 16

__device__ __forceinline__ uint32_t pack_h2(float a, float b) {
    __half2 h = __floats2half2_rn(a, b);
    return *reinterpret_cast<uint32_t*>(&h);
}

__global__ __launch_bounds__(256, 2) void gemm_fp16_kernel(
    const float* __restrict__ x,
    const float* __restrict__ W,
    const float* __restrict__ b)
{
    __shared__ uint32_t As[2][8 * SSTRIDE];
    __shared__ uint32_t Bs[2][8 * SSTRIDE];

    const int tid  = threadIdx.x;
    const int lane = tid & 31;
    const int warp = tid >> 5;
    const int wm   = warp >> 1;
    const int wn   = warp & 1;
    const int block_m = blockIdx.x * GBM;
    const int grp = lane >> 2;
    const int qid = lane & 3;

    const int idx0 = tid * 2;
    const int row0 = idx0 >> 2;
    const int kq0  = (idx0 & 3) * 4;
    const int row1 = (idx0 + 1) >> 2;
    const int kq1  = ((idx0 + 1) & 3) * 4;
    const int gm0 = block_m + row0;
    const int gm1 = block_m + row1;
    const bool ok0 = (gm0 < NNODES);
    const bool ok1 = (gm1 < NNODES);

    float acc[2][8][4];
    #pragma unroll
    for (int i = 0; i < 2; i++)
        #pragma unroll
        for (int j = 0; j < 8; j++)
            #pragma unroll
            for (int c = 0; c < 4; c++)
                acc[i][j][c] = 0.f;

    float4 pa0, pa1, pb0, pb1;

    pa0 = ok0 ? *reinterpret_cast<const float4*>(x + (size_t)gm0 * IN_C + kq0)
              : make_float4(0.f, 0.f, 0.f, 0.f);
    pa1 = ok1 ? *reinterpret_cast<const float4*>(x + (size_t)gm1 * IN_C + kq1)
              : make_float4(0.f, 0.f, 0.f, 0.f);
    pb0 = *reinterpret_cast<const float4*>(W + (size_t)row0 * IN_C + kq0);
    pb1 = *reinterpret_cast<const float4*>(W + (size_t)row1 * IN_C + kq1);

    {
        As[0][((kq0 >> 1) + 0) * SSTRIDE + row0] = pack_h2(pa0.x, pa0.y);
        As[0][((kq0 >> 1) + 1) * SSTRIDE + row0] = pack_h2(pa0.z, pa0.w);
        As[0][((kq1 >> 1) + 0) * SSTRIDE + row1] = pack_h2(pa1.x, pa1.y);
        As[0][((kq1 >> 1) + 1) * SSTRIDE + row1] = pack_h2(pa1.z, pa1.w);
        Bs[0][((kq0 >> 1) + 0) * SSTRIDE + row0] = pack_h2(pb0.x, pb0.y);
        Bs[0][((kq0 >> 1) + 1) * SSTRIDE + row0] = pack_h2(pb0.z, pb0.w);
        Bs[0][((kq1 >> 1) + 0) * SSTRIDE + row1] = pack_h2(pb1.x, pb1.y);
        Bs[0][((kq1 >> 1) + 1) * SSTRIDE + row1] = pack_h2(pb1.z, pb1.w);
    }
    __syncthreads();

    for (int t = 0; t < NTILES; t++) {
        const int cur = t & 1;
        const bool has_next = (t + 1 < NTILES);

        if (has_next) {
            int k0 = (t + 1) * GBK;
            pa0 = ok0 ? *reinterpret_cast<const float4*>(x + (size_t)gm0 * IN_C + k0 + kq0)
                      : make_float4(0.f, 0.f, 0.f, 0.f);
            pa1 = ok1 ? *reinterpret_cast<const float4*>(x + (size_t)gm1 * IN_C + k0 + kq1)
                      : make_float4(0.f, 0.f, 0.f, 0.f);
            pb0 = *reinterpret_cast<const float4*>(W + (size_t)row0 * IN_C + k0 + kq0);
            pb1 = *reinterpret_cast<const float4*>(W + (size_t)row1 * IN_C + k0 + kq1);
        }

        {
            uint32_t af[2][4];
            #pragma unroll
            for (int i = 0; i < 2; i++) {
                int rm = wm * 32 + i * 16 + grp;
                af[i][0] = As[cur][qid * SSTRIDE + rm];
                af[i][1] = As[cur][qid * SSTRIDE + rm + 8];
                af[i][2] = As[cur][(qid + 4) * SSTRIDE + rm];
                af[i][3] = As[cur][(qid + 4) * SSTRIDE + rm + 8];
            }
            uint32_t bf[8][2];
            #pragma unroll
            for (int j = 0; j < 8; j++) {
                int bn = wn * 64 + j * 8 + grp;
                bf[j][0] = Bs[cur][qid * SSTRIDE + bn];
                bf[j][1] = Bs[cur][(qid + 4) * SSTRIDE + bn];
            }
            #pragma unroll
            for (int i = 0; i < 2; i++)
                #pragma unroll
                for (int j = 0; j < 8; j++) {
                    asm volatile(
                        "mma.sync.aligned.m16n8k16.row.col.f32.f16.f16.f32 "
                        "{%0,%1,%2,%3}, {%4,%5,%6,%7}, {%8,%9}, {%0,%1,%2,%3};\n"
                        : "+f"(acc[i][j][0]), "+f"(acc[i][j][1]),
                          "+f"(acc[i][j][2]), "+f"(acc[i][j][3])
                        : "r"(af[i][0]), "r"(af[i][1]), "r"(af[i][2]), "r"(af[i][3]),
                          "r"(bf[j][0]), "r"(bf[j][1]));
                }
        }

        if (has_next) {
            const int nxt = cur ^ 1;
            As[nxt][((kq0 >> 1) + 0) * SSTRIDE + row0] = pack_h2(pa0.x, pa0.y);
            As[nxt][((kq0 >> 1) + 1) * SSTRIDE + row0] = pack_h2(pa0.z, pa0.w);
            As[nxt][((kq1 >> 1) + 0) * SSTRIDE + row1] = pack_h2(pa1.x, pa1.y);
            As[nxt][((kq1 >> 1) + 1) * SSTRIDE + row1] = pack_h2(pa1.z, pa1.w);
            Bs[nxt][((kq0 >> 1) + 0) * SSTRIDE + row0] = pack_h2(pb0.x, pb0.y);
            Bs[nxt][((kq0 >> 1) + 1) * SSTRIDE + row0] = pack_h2(pb0.z, pb0.w);
            Bs[nxt][((kq1 >> 1) + 0) * SSTRIDE + row1] = pack_h2(pb1.x, pb1.y);
            Bs[nxt][((kq1 >> 1) + 1) * SSTRIDE + row1] = pack_h2(pb1.z, pb1.w);
            __syncthreads();
        }
    }

    #pragma unroll
    for (int i = 0; i < 2; i++) {
        int r0 = block_m + wm * 32 + i * 16 + grp;
        int r1 = r0 + 8;
        #pragma unroll
        for (int j = 0; j < 8; j++) {
            int col = wn * 64 + j * 8 + qid * 2;
            float b0 = b[col], b1 = b[col + 1];
            if (r0 < NNODES) {
                __half2 h = __floats2half2_rn(acc[i][j][0] + b0, acc[i][j][1] + b1);
                *reinterpret_cast<__half2*>(&g_y[(size_t)r0 * OUT_C + col]) = h;
            }
            if (r1 < NNODES) {
                __half2 h = __floats2half2_rn(acc[i][j][2] + b0, acc[i][j][3] + b1);
                *reinterpret_cast<__half2*>(&g_y[(size_t)r1 * OUT_C + col]) = h;
            }
        }
    }
}

// ---------------------------------------------------------------------------
// K5: gather + mean. ONE node per warp; lane covers 4 halfs (uint2, 8B);
// 32 lanes x 8B = one full 256B row per request; no intra-warp degree
// divergence. fp32 accumulation, unrolled x8 for MLP.
// ---------------------------------------------------------------------------
__device__ __forceinline__ void acc_row4(float* acc, uint2 v) {
    float2 f;
    f = __half22float2(*reinterpret_cast<__half2*>(&v.x)); acc[0] += f.x; acc[1] += f.y;
    f = __half22float2(*reinterpret_cast<__half2*>(&v.y)); acc[2] += f.x; acc[3] += f.y;
}

__global__ __launch_bounds__(256) void gather_kernel(float* __restrict__ out) {
    int node = (blockIdx.x * blockDim.x + threadIdx.x) >> 5;
    int lane = threadIdx.x & 31;
    if (node >= NNODES) return;

    int s = g_off[node];
    int e = g_off[node + 1];

    float acc[4];
    #pragma unroll
    for (int c = 0; c < 4; c++) acc[c] = 0.f;

    const size_t loff = (size_t)lane * 4;   // half offset within row

    int i = s;
    for (; i + 7 < e; i += 8) {
        int sn[8];
        #pragma unroll
        for (int q = 0; q < 8; q++) sn[q] = __ldg(&g_srcs[i + q]);
        uint2 v[8];
        #pragma unroll
        for (int q = 0; q < 8; q++)
            v[q] = *reinterpret_cast<const uint2*>(&g_y[(size_t)sn[q] * OUT_C + loff]);
        #pragma unroll
        for (int q = 0; q < 8; q++) acc_row4(acc, v[q]);
    }
    for (; i + 3 < e; i += 4) {
        int sn[4];
        #pragma unroll
        for (int q = 0; q < 4; q++) sn[q] = __ldg(&g_srcs[i + q]);
        uint2 v[4];
        #pragma unroll
        for (int q = 0; q < 4; q++)
            v[q] = *reinterpret_cast<const uint2*>(&g_y[(size_t)sn[q] * OUT_C + loff]);
        #pragma unroll
        for (int q = 0; q < 4; q++) acc_row4(acc, v[q]);
    }
    for (; i < e; i++) {
        int s0 = __ldg(&g_srcs[i]);
        uint2 v = *reinterpret_cast<const uint2*>(&g_y[(size_t)s0 * OUT_C + loff]);
        acc_row4(acc, v);
    }

    float inv = 1.0f / (float)max(e - s, 1);
    float4 o = make_float4(acc[0] * inv, acc[1] * inv, acc[2] * inv, acc[3] * inv);
    *reinterpret_cast<float4*>(&out[(size_t)node * OUT_C + loff]) = o;
}

// ---------------------------------------------------------------------------
extern "C" void kernel_launch(void* const* d_in, const int* in_sizes, int n_in,
                              void* d_out, int out_size) {
    const float* x  = (const float*)d_in[0];
    const int*   ei = (const int*)d_in[1];
    const float* W  = (const float*)d_in[2];
    const float* b  = (const float*)d_in[3];
    float* out = (float*)d_out;

    static cudaStream_t s_gemm = nullptr;
    static cudaEvent_t ev_fork = nullptr, ev_join = nullptr;
    if (!s_gemm) {
        cudaStreamCreateWithFlags(&s_gemm, cudaStreamNonBlocking);
        cudaEventCreateWithFlags(&ev_fork, cudaEventDisableTiming);
        cudaEventCreateWithFlags(&ev_join, cudaEventDisableTiming);
    }

    int edge_blocks4 = (NEDGES / 4 + 255) / 256;   // rank: 4 edges/thread
    int edge_blocks2 = (NEDGES / 2 + 255) / 256;   // fill: 2 edges/thread

    // Fork: GEMM on side stream (independent of CSR build)
    cudaEventRecord(ev_fork, 0);
    cudaStreamWaitEvent(s_gemm, ev_fork, 0);
    gemm_fp16_kernel<<<(NNODES + GBM - 1) / GBM, 256, 0, s_gemm>>>(x, W, b);
    cudaEventRecord(ev_join, s_gemm);

    // CSR build on main stream (g_deg, g_blk_state are zero at entry)
    rank_kernel<<<edge_blocks4, 256>>>(ei);
    scan_lookback_kernel<<<NB3, 256>>>();
    fill_kernel<<<edge_blocks2, 256>>>(ei);

    // Join, then gather + mean (one warp per node)
    cudaStreamWaitEvent(0, ev_join, 0);
    gather_kernel<<<(NNODES * 32 + 255) / 256, 256>>>(out);
}